// round 1
// baseline (speedup 1.0000x reference)
#include <cuda_runtime.h>

// MatrixVectorScaledDotProductAttention on GB300.
// Shapes (fixed by the problem): q[512,128] f32, k[512,2048,128] f32, v[512,2048,128] f32.
// Output tuple: out[512,128] f32 followed by attn[512,2048] f32 in d_out.
//
// HBM-bound streaming kernel: 1 CTA per batch row, warp-per-row dot products,
// block softmax in smem, warp-strided weighted-sum of v.

constexpr int NB = 512;
constexpr int L  = 2048;
constexpr int D  = 128;
constexpr float INV_T = 1.0f / 11.313708498984761f;  // 1/sqrt(128)

constexpr int THREADS = 256;
constexpr int WARPS   = THREADS / 32;

__global__ __launch_bounds__(THREADS, 4)
void mvsdpa_kernel(const float* __restrict__ q,
                   const float* __restrict__ k,
                   const float* __restrict__ v,
                   float* __restrict__ out,    // [NB, D]
                   float* __restrict__ attn)   // [NB, L]
{
    __shared__ float s[L];               // 8 KB: scores, then exp(scores - max)
    __shared__ float red[WARPS];         // cross-warp reduce scratch
    __shared__ float acc_s[WARPS * D];   // 4 KB: per-warp output partials

    const int b    = blockIdx.x;
    const int tid  = threadIdx.x;
    const int lane = tid & 31;
    const int w    = tid >> 5;

    // Each lane caches its 4 components of q[b]: lane covers dims [4*lane, 4*lane+4)
    const float4 q4 = *reinterpret_cast<const float4*>(q + (size_t)b * D + lane * 4);

    const float* kb = k + (size_t)b * L * D;
    const float* vb = v + (size_t)b * L * D;

    // ---- Phase 1: scores s[l] = (q . k_l) / T  (one warp per row) ----
    #pragma unroll 4
    for (int l = w; l < L; l += WARPS) {
        float4 k4 = *reinterpret_cast<const float4*>(kb + (size_t)l * D + lane * 4);
        float p = q4.x * k4.x + q4.y * k4.y + q4.z * k4.z + q4.w * k4.w;
        #pragma unroll
        for (int o = 16; o > 0; o >>= 1)
            p += __shfl_xor_sync(0xffffffffu, p, o);
        if (lane == 0) s[l] = p * INV_T;
    }
    __syncthreads();

    // ---- Phase 2: softmax over L ----
    // block max
    float m = -1e30f;
    for (int i = tid; i < L; i += THREADS) m = fmaxf(m, s[i]);
    #pragma unroll
    for (int o = 16; o > 0; o >>= 1)
        m = fmaxf(m, __shfl_xor_sync(0xffffffffu, m, o));
    if (lane == 0) red[w] = m;
    __syncthreads();
    m = red[0];
    #pragma unroll
    for (int j = 1; j < WARPS; j++) m = fmaxf(m, red[j]);
    __syncthreads();   // everyone done reading red before it is reused for sum

    // exp + block sum (store unnormalized exp back into s)
    float sum = 0.f;
    for (int i = tid; i < L; i += THREADS) {
        float e = __expf(s[i] - m);
        s[i] = e;
        sum += e;
    }
    #pragma unroll
    for (int o = 16; o > 0; o >>= 1)
        sum += __shfl_xor_sync(0xffffffffu, sum, o);
    if (lane == 0) red[w] = sum;
    __syncthreads();
    sum = 0.f;
    #pragma unroll
    for (int j = 0; j < WARPS; j++) sum += red[j];
    const float inv = 1.0f / sum;

    // ---- attn output (coalesced) ----
    for (int i = tid; i < L; i += THREADS)
        attn[(size_t)b * L + i] = s[i] * inv;

    // ---- Phase 3: out = sum_l p_l * v_l  (warp-strided streaming of v) ----
    float4 acc = make_float4(0.f, 0.f, 0.f, 0.f);
    #pragma unroll 4
    for (int l = w; l < L; l += WARPS) {
        float p = s[l];  // unnormalized; apply inv once at the end
        float4 v4 = *reinterpret_cast<const float4*>(vb + (size_t)l * D + lane * 4);
        acc.x += p * v4.x;
        acc.y += p * v4.y;
        acc.z += p * v4.z;
        acc.w += p * v4.w;
    }
    *reinterpret_cast<float4*>(acc_s + w * D + lane * 4) = acc;
    __syncthreads();

    if (tid < D) {
        float o = 0.f;
        #pragma unroll
        for (int j = 0; j < WARPS; j++) o += acc_s[j * D + tid];
        out[(size_t)b * D + tid] = o * inv;
    }
}

extern "C" void kernel_launch(void* const* d_in, const int* in_sizes, int n_in,
                              void* d_out, int out_size) {
    const float* q = (const float*)d_in[0];
    const float* k = (const float*)d_in[1];
    const float* v = (const float*)d_in[2];
    float* out  = (float*)d_out;             // [NB, D]
    float* attn = (float*)d_out + NB * D;    // [NB, L]
    mvsdpa_kernel<<<NB, THREADS>>>(q, k, v, out, attn);
}

// round 2
// speedup vs baseline: 1.0863x; 1.0863x over previous
#include <cuda_runtime.h>

// MatrixVectorScaledDotProductAttention on GB300 — single-pass fused version.
// q[512,128] f32, k[512,2048,128] f32, v[512,2048,128] f32.
// Output tuple: out[512,128] f32 then attn[512,2048] f32.
//
// One streaming loop reads k[l] and v[l] together; per-warp online softmax
// (flash-style) with rare rescale branch. Raw scores kept in smem so the
// exact attn matrix is emitted at the end via one coalesced re-exp pass.

constexpr int NB = 512;
constexpr int L  = 2048;
constexpr int D  = 128;
constexpr float INV_T = 1.0f / 11.313708498984761f;  // 1/sqrt(128)

constexpr int THREADS = 256;
constexpr int WARPS   = THREADS / 32;

__global__ __launch_bounds__(THREADS, 4)
void mvsdpa_fused_kernel(const float* __restrict__ q,
                         const float* __restrict__ k,
                         const float* __restrict__ v,
                         float* __restrict__ out,    // [NB, D]
                         float* __restrict__ attn)   // [NB, L]
{
    __shared__ float s[L];                 // 8 KB raw scores
    __shared__ float red_m[WARPS];
    __shared__ float red_s[WARPS];
    __shared__ float acc_s[WARPS * D];     // 4 KB per-warp output partials

    const int b    = blockIdx.x;
    const int tid  = threadIdx.x;
    const int lane = tid & 31;
    const int w    = tid >> 5;

    // Lane's 4 components of q[b] (dims [4*lane, 4*lane+4))
    const float4 q4 = *reinterpret_cast<const float4*>(q + (size_t)b * D + lane * 4);

    const float* kb = k + (size_t)b * L * D;
    const float* vb = v + (size_t)b * L * D;

    // ---- Fused pass: score + online softmax + weighted v-accumulate ----
    float m   = -1e30f;
    float sum = 0.f;
    float4 acc = make_float4(0.f, 0.f, 0.f, 0.f);

    #pragma unroll 4
    for (int l = w; l < L; l += WARPS) {
        const float* krow = kb + (size_t)l * D + lane * 4;
        const float* vrow = vb + (size_t)l * D + lane * 4;
        float4 k4 = *reinterpret_cast<const float4*>(krow);
        float4 v4 = *reinterpret_cast<const float4*>(vrow);

        float p = k4.x * q4.x + k4.y * q4.y + k4.z * q4.z + k4.w * q4.w;
        #pragma unroll
        for (int o = 16; o > 0; o >>= 1)
            p += __shfl_xor_sync(0xffffffffu, p, o);
        float score = p * INV_T;
        if (lane == 0) s[l] = score;

        if (score > m) {                       // rare, warp-uniform
            float c = __expf(m - score);
            sum *= c;
            acc.x *= c; acc.y *= c; acc.z *= c; acc.w *= c;
            m = score;
        }
        float e = __expf(score - m);
        sum += e;
        acc.x += e * v4.x;
        acc.y += e * v4.y;
        acc.z += e * v4.z;
        acc.w += e * v4.w;
    }

    if (lane == 0) { red_m[w] = m; red_s[w] = sum; }
    __syncthreads();

    // Global max + corrected global sum (every thread redundantly, cheap)
    float M = red_m[0];
    #pragma unroll
    for (int j = 1; j < WARPS; j++) M = fmaxf(M, red_m[j]);
    float sumtot = 0.f;
    #pragma unroll
    for (int j = 0; j < WARPS; j++) sumtot += red_s[j] * __expf(red_m[j] - M);
    const float inv = 1.0f / sumtot;

    // Rescale this warp's accumulator to the global max and stash
    const float scale = __expf(m - M);
    acc.x *= scale; acc.y *= scale; acc.z *= scale; acc.w *= scale;
    *reinterpret_cast<float4*>(acc_s + w * D + lane * 4) = acc;
    __syncthreads();

    // ---- attn output: exp(s - M) * inv, coalesced float4 stores ----
    {
        const float4* s4p = reinterpret_cast<const float4*>(s);
        float4* a4p = reinterpret_cast<float4*>(attn + (size_t)b * L);
        #pragma unroll
        for (int i = tid; i < L / 4; i += THREADS) {
            float4 sv = s4p[i];
            float4 av;
            av.x = __expf(sv.x - M) * inv;
            av.y = __expf(sv.y - M) * inv;
            av.z = __expf(sv.z - M) * inv;
            av.w = __expf(sv.w - M) * inv;
            a4p[i] = av;
        }
    }

    // ---- out: combine per-warp partials over D ----
    if (tid < D) {
        float o = 0.f;
        #pragma unroll
        for (int j = 0; j < WARPS; j++) o += acc_s[j * D + tid];
        out[(size_t)b * D + tid] = o * inv;
    }
}

extern "C" void kernel_launch(void* const* d_in, const int* in_sizes, int n_in,
                              void* d_out, int out_size) {
    const float* q = (const float*)d_in[0];
    const float* k = (const float*)d_in[1];
    const float* v = (const float*)d_in[2];
    float* out  = (float*)d_out;             // [NB, D]
    float* attn = (float*)d_out + NB * D;    // [NB, L]
    mvsdpa_fused_kernel<<<NB, THREADS>>>(q, k, v, out, attn);
}